// round 9
// baseline (speedup 1.0000x reference)
#include <cuda_runtime.h>
#include <math_constants.h>

// Tropical (max-plus) depthwise 5x5 conv, stride=1, pad=2, dil=1.
// x: (8,32,224,224) f32, kernel: (32,1,5,5) f32, out same shape as x.
// out[b,c,y,x] = max_{i,j} x[b,c, y+i-2, x+j-2] + kernel[c,0,4-i,4-j]
//
// R7: alu-pipe-bound (FMNMX + integer overhead). 16 outputs/thread
// (4 rows x 4 cols), row-owned tile fill with per-thread y-predicate and
// immediate-offset loads. Weights in __constant__ (UR operands).

#define TW 32
#define TH 112
#define SW 36    // TW + 4 halo
#define SH 116   // TH + 4 halo

static constexpr int Hdim = 224;
static constexpr int Wdim = 224;

__constant__ float cw[32 * 25];   // raw (unflipped) kernel from d_in[1]

// flipped weight (i,j): kernel[c,0,4-i,4-j] = cw[base + 24 - (5i+j)]
#define WGT(i, j) cw[wbase + (24 - ((i) * 5 + (j)))]

__global__ __launch_bounds__(224, 7)
void tropical_conv_kernel(const float* __restrict__ x,
                          float* __restrict__ out) {
    __shared__ __align__(16) float sm[SH * SW];

    const int tid = threadIdx.x;
    const int bc  = blockIdx.z;          // b*32 + c
    const int wbase = (bc & 31) * 25;    // block-uniform
    const int gx0 = blockIdx.x * TW;
    const int gy0 = blockIdx.y * TH;

    const float* __restrict__ xp = x + (size_t)bc * (Hdim * Wdim);

    // ---- Tile fill pass A: rows 0..111. Each thread owns half a shared row
    // (9 float2). y-predicate once per thread; only pair p=0 (gx0==0) and
    // p=17 (gx0==192) ever need an x-boundary check.
    {
        const int r    = tid >> 1;       // 0..111
        const int half = tid & 1;
        const int gy   = gy0 + r - 2;
        const bool yok = (unsigned)gy < (unsigned)Hdim;
        const float* rowp = xp + gy * Wdim + (gx0 - 2 + 18 * half);
        float* srow = sm + r * SW + 18 * half;
        #pragma unroll
        for (int k = 0; k < 9; k++) {
            bool ok = yok;
            if (k == 0) ok = ok && !(half == 0 && gx0 == 0);
            if (k == 8) ok = ok && !(half == 1 && gx0 == 192);
            float2 v = make_float2(-CUDART_INF_F, -CUDART_INF_F);
            if (ok) v = *reinterpret_cast<const float2*>(rowp + 2 * k);
            *reinterpret_cast<float2*>(srow + 2 * k) = v;
        }
    }
    // ---- Pass B: rows 112..115 (72 pairs, threads 0..71).
    if (tid < 72) {
        const int rr = tid / 18;         // 0..3
        const int p  = tid - rr * 18;
        const int r2 = 112 + rr;
        const int gy  = gy0 + r2 - 2;
        const int gxs = gx0 + 2 * p - 2;
        float2 v = make_float2(-CUDART_INF_F, -CUDART_INF_F);
        if ((unsigned)gy < (unsigned)Hdim && (unsigned)gxs < (unsigned)Wdim)
            v = *reinterpret_cast<const float2*>(xp + gy * Wdim + gxs);
        *reinterpret_cast<float2*>(sm + r2 * SW + 2 * p) = v;
    }
    __syncthreads();

    // ---- Compute: tx 0..7 (4-wide col group), ty 0..27 (4 output rows each).
    // Warp phases (8 lanes) share ty -> LDS.128 conflict-free.
    const int tx = tid & 7;
    const int ty = tid >> 3;
    const float* smb = sm + (4 * ty) * SW + 4 * tx;   // 16B-aligned

    float acc[4][4];

    #pragma unroll
    for (int r = 0; r < 8; r++) {
        const float4 lo = *reinterpret_cast<const float4*>(smb + r * SW);
        const float4 hi = *reinterpret_cast<const float4*>(smb + r * SW + 4);
        const float xv[8] = {lo.x, lo.y, lo.z, lo.w, hi.x, hi.y, hi.z, hi.w};

        #pragma unroll
        for (int k = 0; k < 4; k++) {
            const int i = r - k;         // weight row for acc row k
            if (i == 0) {
                // first touch of acc row k: init from tap j=0
                #pragma unroll
                for (int t = 0; t < 4; t++) acc[k][t] = xv[t] + WGT(0, 0);
                #pragma unroll
                for (int j = 1; j < 5; j++)
                    #pragma unroll
                    for (int t = 0; t < 4; t++)
                        acc[k][t] = fmaxf(acc[k][t], xv[t + j] + WGT(0, j));
            } else if (i > 0 && i < 5) {
                #pragma unroll
                for (int j = 0; j < 5; j++)
                    #pragma unroll
                    for (int t = 0; t < 4; t++)
                        acc[k][t] = fmaxf(acc[k][t], xv[t + j] + WGT(i, j));
            }
        }
    }

    float* __restrict__ op = out + (size_t)bc * (Hdim * Wdim)
                           + (gy0 + 4 * ty) * Wdim + gx0 + 4 * tx;
    #pragma unroll
    for (int k = 0; k < 4; k++)
        *reinterpret_cast<float4*>(op + k * Wdim) =
            make_float4(acc[k][0], acc[k][1], acc[k][2], acc[k][3]);
}

extern "C" void kernel_launch(void* const* d_in, const int* in_sizes, int n_in,
                              void* d_out, int out_size) {
    const float* x = (const float*)d_in[0];
    float* out = (float*)d_out;

    // Stage weights into constant memory (D2D async copy, graph-capturable).
    cudaMemcpyToSymbolAsync(cw, d_in[1], 32 * 25 * sizeof(float), 0,
                            cudaMemcpyDeviceToDevice, 0);

    dim3 grid(Wdim / TW, Hdim / TH, 8 * 32);  // (7, 2, 256)
    tropical_conv_kernel<<<grid, 224>>>(x, out);
}

// round 10
// speedup vs baseline: 1.0524x; 1.0524x over previous
#include <cuda_runtime.h>
#include <math_constants.h>

// Tropical (max-plus) depthwise 5x5 conv, stride=1, pad=2, dil=1.
// x: (8,32,224,224) f32, kernel: (32,1,5,5) f32, out same shape as x.
// out[b,c,y,x] = max_{i,j} x[b,c, y+i-2, x+j-2] + kernel[c,0,4-i,4-j]
//
// R10: latency-bound post-mortem -> back to R6 compute shape (2x4 outputs,
// 8 acc + 8 xv fits in regs, issue ~80%) + R7 row-owned low-alu fill +
// constant-mem weights (UR operands) + 36-reg cap for load hoisting.

#define TW 32
#define TH 56
#define SW 36   // TW + 4 halo
#define SH 60   // TH + 4 halo

static constexpr int Hdim = 224;
static constexpr int Wdim = 224;

__constant__ float cw[32 * 25];   // raw (unflipped) kernel from d_in[1]

// flipped weight (i,j): kernel[c,0,4-i,4-j] = cw[base + 24 - (5i+j)]
#define WGT(i, j) cw[wbase + (24 - ((i) * 5 + (j)))]

__global__ __launch_bounds__(224, 8)
void tropical_conv_kernel(const float* __restrict__ x,
                          float* __restrict__ out) {
    __shared__ __align__(16) float sm[SH * SW];

    const int tid = threadIdx.x;
    const int bc  = blockIdx.z;          // b*32 + c
    const int wbase = (bc & 31) * 25;    // block-uniform -> LDCU/UR
    const int gx0 = blockIdx.x * TW;
    const int gy0 = blockIdx.y * TH;

    const float* __restrict__ xp = x + (size_t)bc * (Hdim * Wdim);

    // ---- Row-owned tile fill: 60 rows x 18 float2 pairs = 1080 pairs.
    // 180 threads own a third-row (6 pairs) each: one y-predicate per thread,
    // immediate offsets, x-check only on global pairs p==0 and p==17.
    if (tid < 180) {
        const int r    = tid / 3;        // 0..59 (magic mul, once)
        const int part = tid - 3 * r;    // 0..2
        const int gy   = gy0 + r - 2;
        const bool yok = (unsigned)gy < (unsigned)Hdim;
        const float* rowp = xp + gy * Wdim + (gx0 - 2 + 12 * part);
        float* srow = sm + r * SW + 12 * part;
        #pragma unroll
        for (int k = 0; k < 6; k++) {
            bool ok = yok;
            if (k == 0) ok = ok && !(part == 0 && gx0 == 0);     // pair p=0
            if (k == 5) ok = ok && !(part == 2 && gx0 == 192);   // pair p=17
            float2 v = make_float2(-CUDART_INF_F, -CUDART_INF_F);
            if (ok) v = *reinterpret_cast<const float2*>(rowp + 2 * k);
            *reinterpret_cast<float2*>(srow + 2 * k) = v;
        }
    }
    __syncthreads();

    // ---- Compute: tx 0..7 (4-wide col group), ty 0..27 (2 output rows).
    // Each LDS.128 phase (8 lanes, same ty) covers all 32 banks: conflict-free.
    const int tx = tid & 7;
    const int ty = tid >> 3;
    const float* smb = sm + (2 * ty) * SW + 4 * tx;   // 16B-aligned

    float accA[4], accB[4];

    #pragma unroll
    for (int r = 0; r < 6; r++) {
        const float4 lo = *reinterpret_cast<const float4*>(smb + r * SW);
        const float4 hi = *reinterpret_cast<const float4*>(smb + r * SW + 4);
        const float xv[8] = {lo.x, lo.y, lo.z, lo.w, hi.x, hi.y, hi.z, hi.w};

        // Output row A (gy0 + 2ty): weight row i = r, valid r in [0,4]
        if (r == 0) {
            #pragma unroll
            for (int t = 0; t < 4; t++) accA[t] = xv[t] + WGT(0, 0);
            #pragma unroll
            for (int j = 1; j < 5; j++)
                #pragma unroll
                for (int t = 0; t < 4; t++)
                    accA[t] = fmaxf(accA[t], xv[t + j] + WGT(0, j));
        } else if (r < 5) {
            #pragma unroll
            for (int j = 0; j < 5; j++)
                #pragma unroll
                for (int t = 0; t < 4; t++)
                    accA[t] = fmaxf(accA[t], xv[t + j] + WGT(r, j));
        }

        // Output row B (gy0 + 2ty + 1): weight row i = r-1, valid r in [1,5]
        if (r == 1) {
            #pragma unroll
            for (int t = 0; t < 4; t++) accB[t] = xv[t] + WGT(0, 0);
            #pragma unroll
            for (int j = 1; j < 5; j++)
                #pragma unroll
                for (int t = 0; t < 4; t++)
                    accB[t] = fmaxf(accB[t], xv[t + j] + WGT(0, j));
        } else if (r >= 2) {
            #pragma unroll
            for (int j = 0; j < 5; j++)
                #pragma unroll
                for (int t = 0; t < 4; t++)
                    accB[t] = fmaxf(accB[t], xv[t + j] + WGT(r - 1, j));
        }
    }

    float* __restrict__ op = out + (size_t)bc * (Hdim * Wdim)
                           + (gy0 + 2 * ty) * Wdim + gx0 + 4 * tx;
    *reinterpret_cast<float4*>(op)        = make_float4(accA[0], accA[1], accA[2], accA[3]);
    *reinterpret_cast<float4*>(op + Wdim) = make_float4(accB[0], accB[1], accB[2], accB[3]);
}

extern "C" void kernel_launch(void* const* d_in, const int* in_sizes, int n_in,
                              void* d_out, int out_size) {
    const float* x = (const float*)d_in[0];
    float* out = (float*)d_out;

    // Stage weights into constant memory (D2D async copy, graph-capturable).
    cudaMemcpyToSymbolAsync(cw, d_in[1], 32 * 25 * sizeof(float), 0,
                            cudaMemcpyDeviceToDevice, 0);

    dim3 grid(Wdim / TW, Hdim / TH, 8 * 32);  // (7, 4, 256)
    tropical_conv_kernel<<<grid, 224>>>(x, out);
}